// round 11
// baseline (speedup 1.0000x reference)
#include <cuda_runtime.h>
#include <cuda_fp16.h>

#define HW 4096          // tokens
#define NH 8             // heads
#define CHUNK 256        // keys per smem stage
#define CPAD 132         // padded uint stride for V^T rows (CHUNK/2 + 4)
#define KS 2             // key split for attention (partials add exactly)

// ---- scratch (device globals; no allocation allowed) ----
__device__ __align__(16) __half g_qh[NH * HW * 8];  // [h][n][8] f16, L2-norm * T*log2e
__device__ __align__(16) __half g_kh[NH * HW * 8];  // [h][m][8] f16, L2-norm
__device__ __align__(16) __half g_vt[NH * 8 * HW];  // [h][d][m] f16 (V transposed)
__device__ float g_pacc[KS * 64 * HW];              // partial numerators [s][h*8+d][p]
__device__ float g_pden[KS * NH * HW];              // partial denominators [s][h][p]

// pack two f32 -> f16x2
__device__ __forceinline__ unsigned packh2(float lo, float hi) {
    unsigned r; asm("cvt.rn.f16x2.f32 %0,%1,%2;" : "=r"(r) : "f"(hi), "f"(lo)); return r;
}
// packed half2 exp2
__device__ __forceinline__ unsigned ex2h2(unsigned x) {
    unsigned r; asm("ex2.approx.f16x2 %0,%1;" : "=r"(r) : "r"(x)); return r;
}
// S-mma: m16n8k8 f16 inputs, f32 accumulate, scalar C broadcast (bias)
__device__ __forceinline__ void mma_s(float& d0, float& d1, float& d2, float& d3,
                                      unsigned a0, unsigned a1, unsigned b0,
                                      float c) {
    asm("mma.sync.aligned.m16n8k8.row.col.f32.f16.f16.f32 "
        "{%0,%1,%2,%3},{%4,%5},{%6},{%7,%7,%7,%7};"
        : "=f"(d0), "=f"(d1), "=f"(d2), "=f"(d3)
        : "r"(a0), "r"(a1), "r"(b0), "f"(c));
}
// m16n8k16 f16 mma, accumulates in place
__device__ __forceinline__ void mma16(float& d0, float& d1, float& d2, float& d3,
                                      unsigned a0, unsigned a1, unsigned a2, unsigned a3,
                                      unsigned b0, unsigned b1) {
    asm("mma.sync.aligned.m16n8k16.row.col.f32.f16.f16.f32 "
        "{%0,%1,%2,%3},{%4,%5,%6,%7},{%8,%9},{%0,%1,%2,%3};"
        : "+f"(d0), "+f"(d1), "+f"(d2), "+f"(d3)
        : "r"(a0), "r"(a1), "r"(a2), "r"(a3), "r"(b0), "r"(b1));
}

// ============================================================================
// Kernel 1: q/k/v projection + per-head L2 norm; emit f16.
// TWO heads (16 output rows) per task: 16 accumulators, input element loaded
// once -> 2x FMA-per-load ILP, half the redundant global reads.
// grid = (32, 12), block = 128. task y: 0..3 q, 4..7 k, 8..11 v.
// ============================================================================
__global__ __launch_bounds__(128)
void prep_kernel(const float* __restrict__ x, const float* __restrict__ y,
                 const float* __restrict__ wq, const float* __restrict__ wkv,
                 const float* __restrict__ temperature) {
    __shared__ float sWT[64 * 16];   // [c][16 rows], 4 KB
    const int tid  = threadIdx.x;
    const int p    = blockIdx.x * 128 + tid;
    const int task = blockIdx.y;
    const int typ  = task >> 2;      // 0=q, 1=k, 2=v
    const int sub  = task & 3;       // head pair: heads 2*sub, 2*sub+1

    const float* wrow;
    if (typ == 0)      wrow = wq  + (sub * 16) * 64;
    else if (typ == 1) wrow = wkv + (sub * 16) * 64;
    else               wrow = wkv + (64 + sub * 16) * 64;
#pragma unroll
    for (int i = tid; i < 1024; i += 128) {     // coalesced
        const int d = i >> 6, c = i & 63;
        sWT[c * 16 + d] = wrow[i];
    }
    __syncthreads();

    const float* __restrict__ src = (typ == 0) ? x : y;
    float acc[16];
#pragma unroll
    for (int d = 0; d < 16; d++) acc[d] = 0.f;

#pragma unroll
    for (int c = 0; c < 64; c++) {
        const float xv = src[c * HW + p];       // 1 LDG, coalesced
#pragma unroll
        for (int d4 = 0; d4 < 4; d4++) {
            const float4 w = *(const float4*)&sWT[c * 16 + d4 * 4];   // broadcast
            acc[d4 * 4 + 0] += w.x * xv; acc[d4 * 4 + 1] += w.y * xv;
            acc[d4 * 4 + 2] += w.z * xv; acc[d4 * 4 + 3] += w.w * xv;
        }
    }

    if (typ == 2) {
#pragma unroll
        for (int d = 0; d < 16; d++)
            g_vt[((size_t)(sub * 2) * 8 + d) * HW + p] = __float2half_rn(acc[d]);
        return;
    }

#pragma unroll
    for (int hh = 0; hh < 2; hh++) {
        const int h = sub * 2 + hh;
        float ss = 0.f;
#pragma unroll
        for (int d = 0; d < 8; d++) ss += acc[hh * 8 + d] * acc[hh * 8 + d];
        float scale = 1.f / fmaxf(sqrtf(ss), 1e-12f);
        if (typ == 0) scale *= temperature[h] * 1.4426950408889634f;

        __half2 h01 = __floats2half2_rn(acc[hh*8+0] * scale, acc[hh*8+1] * scale);
        __half2 h23 = __floats2half2_rn(acc[hh*8+2] * scale, acc[hh*8+3] * scale);
        __half2 h45 = __floats2half2_rn(acc[hh*8+4] * scale, acc[hh*8+5] * scale);
        __half2 h67 = __floats2half2_rn(acc[hh*8+6] * scale, acc[hh*8+7] * scale);
        uint4 row;
        row.x = *(unsigned*)&h01; row.y = *(unsigned*)&h23;
        row.z = *(unsigned*)&h45; row.w = *(unsigned*)&h67;
        uint4* dst = (typ == 0) ? (uint4*)g_qh : (uint4*)g_kh;
        dst[(size_t)h * HW + p] = row;
    }
}

// ============================================================================
// Kernel 2: flash attention on HMMA, key-split 2 ways for occupancy.
// Block = 256 thr (8 warps), warp owns 16 queries; block covers 128 queries
// of one head over half the keys. grid = (32, 8, 2) = 512 blocks.
// Constant-bias softmax => partials across key halves add exactly.
// Denominator via extra mma against ones (f32, exact row-sum of same f16 P).
// ============================================================================
__global__ __launch_bounds__(256)
void attn_kernel(const float* __restrict__ temperature) {
    __shared__ unsigned sK[CHUNK * 4];      // 4 KB
    __shared__ unsigned sVT[8 * CPAD];      // 4.2 KB

    const int h    = blockIdx.y;
    const int s    = blockIdx.z;
    const int tid  = threadIdx.x;
    const int wid  = tid >> 5;
    const int lane = tid & 31;
    const int r = lane >> 2, m = lane & 3;
    const int q0 = blockIdx.x * 128 + wid * 16;

    const float bias = -fabsf(temperature[h]) * 1.4426950408889634f;
    const unsigned ONES = 0x3C003C00u;

    const unsigned* qU = (const unsigned*)g_qh + (size_t)h * HW * 4;
    const unsigned a0q = qU[(q0 + r) * 4 + m];
    const unsigned a1q = qU[(q0 + r + 8) * 4 + m];

    float o0 = 0.f, o1 = 0.f, o2 = 0.f, o3 = 0.f;
    float dd0 = 0.f, dd1 = 0.f, dd2 = 0.f, dd3 = 0.f;

    const uint4*    gK4 = (const uint4*)((const unsigned*)g_kh + (size_t)h * HW * 4);
    const unsigned* gV  = (const unsigned*)g_vt + (size_t)h * 8 * (HW / 2);

    const int vd = tid >> 5;
    const int vj = (tid & 31) * 4;
    const int ch0 = s * (HW / KS / CHUNK);          // 8 chunks per split

    for (int ch = ch0; ch < ch0 + HW / KS / CHUNK; ch++) {
        __syncthreads();
        ((uint4*)sK)[tid] = gK4[ch * CHUNK + tid];
        *(uint4*)(sVT + vd * CPAD + vj) =
            *(const uint4*)(gV + vd * (HW / 2) + ch * (CHUNK / 2) + vj);
        __syncthreads();

#pragma unroll 4
        for (int kb = 0; kb < CHUNK; kb += 16) {
            const unsigned kb0 = sK[(kb + r) * 4 + m];
            const unsigned kb1 = sK[(kb + 8 + r) * 4 + m];

            float s0, s1, s2, s3, t0, t1, t2, t3;
            mma_s(s0, s1, s2, s3, a0q, a1q, kb0, bias);
            mma_s(t0, t1, t2, t3, a0q, a1q, kb1, bias);

            const unsigned p0 = ex2h2(packh2(s0, s1));
            const unsigned p1 = ex2h2(packh2(s2, s3));
            const unsigned p2 = ex2h2(packh2(t0, t1));
            const unsigned p3 = ex2h2(packh2(t2, t3));

            const unsigned vb0 = sVT[r * CPAD + (kb >> 1) + m];
            const unsigned vb1 = sVT[r * CPAD + (kb >> 1) + m + 4];
            mma16(o0, o1, o2, o3, p0, p1, p2, p3, vb0, vb1);
            mma16(dd0, dd1, dd2, dd3, p0, p1, p2, p3, ONES, ONES);
        }
    }

    // partial numerators (undivided) + partial row denominators
    float* pa = g_pacc + ((size_t)s * 64 + h * 8) * HW;
    pa[(2 * m    ) * HW + q0 + r    ] = o0;
    pa[(2 * m + 1) * HW + q0 + r    ] = o1;
    pa[(2 * m    ) * HW + q0 + r + 8] = o2;
    pa[(2 * m + 1) * HW + q0 + r + 8] = o3;
    if (m == 0) {   // dd0/dd2 identical across the quad (B = ones)
        float* pd = g_pden + ((size_t)s * NH + h) * HW;
        pd[q0 + r    ] = dd0;
        pd[q0 + r + 8] = dd2;
    }
}

// ============================================================================
// Kernel 3: fused reduce + output projection.
// out[o][p] = sum_c wout[o][c] * (pacc0[c][p]+pacc1[c][p]) * rden[c/8][p]
// grid = (32, 8), block = 128; 8 outputs per thread.
// ============================================================================
__global__ __launch_bounds__(128)
void outproj_kernel(const float* __restrict__ wout, float* __restrict__ out) {
    __shared__ float sWT[64 * 8];
    const int tid = threadIdx.x;
    const int p   = blockIdx.x * 128 + tid;
    const int og  = blockIdx.y;

#pragma unroll
    for (int i = tid; i < 512; i += 128) {
        const int d = i >> 6, c = i & 63;
        sWT[c * 8 + d] = wout[(og * 8) * 64 + i];
    }
    __syncthreads();

    float rden[8];
#pragma unroll
    for (int h = 0; h < 8; h++)
        rden[h] = 1.f / (g_pden[(size_t)h * HW + p] +
                         g_pden[(size_t)(NH + h) * HW + p]);

    float acc[8];
#pragma unroll
    for (int d = 0; d < 8; d++) acc[d] = 0.f;

#pragma unroll
    for (int c = 0; c < 64; c++) {
        const float xv = (g_pacc[(size_t)c * HW + p] +
                          g_pacc[(size_t)(64 + c) * HW + p]) * rden[c >> 3];
        const float4 w0 = *(const float4*)&sWT[c * 8];
        const float4 w1 = *(const float4*)&sWT[c * 8 + 4];
        acc[0] += w0.x * xv; acc[1] += w0.y * xv;
        acc[2] += w0.z * xv; acc[3] += w0.w * xv;
        acc[4] += w1.x * xv; acc[5] += w1.y * xv;
        acc[6] += w1.z * xv; acc[7] += w1.w * xv;
    }

#pragma unroll
    for (int d = 0; d < 8; d++)
        out[(og * 8 + d) * HW + p] = acc[d];
}

// ============================================================================
extern "C" void kernel_launch(void* const* d_in, const int* in_sizes, int n_in,
                              void* d_out, int out_size) {
    const float* x    = (const float*)d_in[0];
    const float* y    = (const float*)d_in[1];
    const float* wq   = (const float*)d_in[2];
    const float* wkv  = (const float*)d_in[3];
    const float* wout = (const float*)d_in[4];
    const float* temp = (const float*)d_in[5];
    float* out = (float*)d_out;

    prep_kernel<<<dim3(32, 12), 128>>>(x, y, wq, wkv, temp);
    attn_kernel<<<dim3(32, 8, KS), 256>>>(temp);
    outproj_kernel<<<dim3(32, 8), 128>>>(wout, out);
}

// round 12
// speedup vs baseline: 1.1497x; 1.1497x over previous
#include <cuda_runtime.h>
#include <cuda_fp16.h>

#define HW 4096          // tokens
#define NH 8             // heads
#define CHUNK 256        // keys per smem stage
#define CPAD 132         // padded uint stride for V^T rows (CHUNK/2 + 4)
#define KS 4             // key split for attention (partials add exactly)

// ---- scratch (device globals; no allocation allowed) ----
__device__ __align__(16) __half g_qh[NH * HW * 8];  // [h][n][8] f16, L2-norm * T*log2e
__device__ __align__(16) __half g_kh[NH * HW * 8];  // [h][m][8] f16, L2-norm
__device__ __align__(16) __half g_vt[NH * 8 * HW];  // [h][d][m] f16 (V transposed)
__device__ float g_pacc[KS * 64 * HW];              // partial numerators [s][h*8+d][p]
__device__ float g_pden[KS * NH * HW];              // partial denominators [s][h][p]
__device__ float g_o[64 * HW];                      // reduced attention out [c][p]

// pack two f32 -> f16x2
__device__ __forceinline__ unsigned packh2(float lo, float hi) {
    unsigned r; asm("cvt.rn.f16x2.f32 %0,%1,%2;" : "=r"(r) : "f"(hi), "f"(lo)); return r;
}
// packed half2 exp2
__device__ __forceinline__ unsigned ex2h2(unsigned x) {
    unsigned r; asm("ex2.approx.f16x2 %0,%1;" : "=r"(r) : "r"(x)); return r;
}
// S-mma: m16n8k8 f16 inputs, f32 accumulate, scalar C broadcast (bias)
__device__ __forceinline__ void mma_s(float& d0, float& d1, float& d2, float& d3,
                                      unsigned a0, unsigned a1, unsigned b0,
                                      float c) {
    asm("mma.sync.aligned.m16n8k8.row.col.f32.f16.f16.f32 "
        "{%0,%1,%2,%3},{%4,%5},{%6},{%7,%7,%7,%7};"
        : "=f"(d0), "=f"(d1), "=f"(d2), "=f"(d3)
        : "r"(a0), "r"(a1), "r"(b0), "f"(c));
}
// m16n8k16 f16 mma, accumulates in place
__device__ __forceinline__ void mma16(float& d0, float& d1, float& d2, float& d3,
                                      unsigned a0, unsigned a1, unsigned a2, unsigned a3,
                                      unsigned b0, unsigned b1) {
    asm("mma.sync.aligned.m16n8k16.row.col.f32.f16.f16.f32 "
        "{%0,%1,%2,%3},{%4,%5,%6,%7},{%8,%9},{%0,%1,%2,%3};"
        : "+f"(d0), "+f"(d1), "+f"(d2), "+f"(d3)
        : "r"(a0), "r"(a1), "r"(a2), "r"(a3), "r"(b0), "r"(b1));
}

// ============================================================================
// Kernel 1: q/k/v projection + per-head L2 norm; emit f16.
// One head per task (occupancy!), TWO pixels per thread via float2 loads:
// per channel 1 LDG.64 + 2 broadcast LDS.128 + 16 FMA.
// grid = (16, 24), block = 128. task y: 0..7 q, 8..15 k, 16..23 v.
// ============================================================================
__global__ __launch_bounds__(128)
void prep_kernel(const float* __restrict__ x, const float* __restrict__ y,
                 const float* __restrict__ wq, const float* __restrict__ wkv,
                 const float* __restrict__ temperature) {
    __shared__ float sWT[64 * 8];    // [c][d], 2 KB
    const int tid  = threadIdx.x;
    const int pp   = blockIdx.x * 128 + tid;   // pixel pair index
    const int p0   = pp * 2;
    const int task = blockIdx.y;
    const int typ  = task >> 3;      // 0=q, 1=k, 2=v
    const int h    = task & 7;

    const float* wrow;
    if (typ == 0)      wrow = wq  + (h * 8) * 64;
    else if (typ == 1) wrow = wkv + (h * 8) * 64;
    else               wrow = wkv + (64 + h * 8) * 64;
#pragma unroll
    for (int i = tid; i < 512; i += 128) {
        const int d = i >> 6, c = i & 63;
        sWT[c * 8 + d] = wrow[i];
    }
    __syncthreads();

    const float* __restrict__ src = (typ == 0) ? x : y;
    float accx[8], accy[8];
#pragma unroll
    for (int d = 0; d < 8; d++) { accx[d] = 0.f; accy[d] = 0.f; }

#pragma unroll
    for (int c = 0; c < 64; c++) {
        const float2 xv = *(const float2*)&src[c * HW + p0];    // 1 LDG.64
        const float4 w0 = *(const float4*)&sWT[c * 8];          // broadcast
        const float4 w1 = *(const float4*)&sWT[c * 8 + 4];
        accx[0] += w0.x * xv.x; accy[0] += w0.x * xv.y;
        accx[1] += w0.y * xv.x; accy[1] += w0.y * xv.y;
        accx[2] += w0.z * xv.x; accy[2] += w0.z * xv.y;
        accx[3] += w0.w * xv.x; accy[3] += w0.w * xv.y;
        accx[4] += w1.x * xv.x; accy[4] += w1.x * xv.y;
        accx[5] += w1.y * xv.x; accy[5] += w1.y * xv.y;
        accx[6] += w1.z * xv.x; accy[6] += w1.z * xv.y;
        accx[7] += w1.w * xv.x; accy[7] += w1.w * xv.y;
    }

    if (typ == 2) {
#pragma unroll
        for (int d = 0; d < 8; d++) {
            __half2 hv = __floats2half2_rn(accx[d], accy[d]);
            *(__half2*)&g_vt[((size_t)h * 8 + d) * HW + p0] = hv;  // 4B aligned
        }
        return;
    }

    const float tscale = (typ == 0) ? temperature[h] * 1.4426950408889634f : 1.f;
    uint4* dst = (typ == 0) ? (uint4*)g_qh : (uint4*)g_kh;

    float ssx = 0.f, ssy = 0.f;
#pragma unroll
    for (int d = 0; d < 8; d++) { ssx += accx[d] * accx[d]; ssy += accy[d] * accy[d]; }
    const float sx = tscale / fmaxf(sqrtf(ssx), 1e-12f);
    const float sy = tscale / fmaxf(sqrtf(ssy), 1e-12f);

    uint4 r0, r1;
    {
        __half2 a = __floats2half2_rn(accx[0]*sx, accx[1]*sx);
        __half2 b = __floats2half2_rn(accx[2]*sx, accx[3]*sx);
        __half2 c = __floats2half2_rn(accx[4]*sx, accx[5]*sx);
        __half2 d = __floats2half2_rn(accx[6]*sx, accx[7]*sx);
        r0.x = *(unsigned*)&a; r0.y = *(unsigned*)&b; r0.z = *(unsigned*)&c; r0.w = *(unsigned*)&d;
    }
    {
        __half2 a = __floats2half2_rn(accy[0]*sy, accy[1]*sy);
        __half2 b = __floats2half2_rn(accy[2]*sy, accy[3]*sy);
        __half2 c = __floats2half2_rn(accy[4]*sy, accy[5]*sy);
        __half2 d = __floats2half2_rn(accy[6]*sy, accy[7]*sy);
        r1.x = *(unsigned*)&a; r1.y = *(unsigned*)&b; r1.z = *(unsigned*)&c; r1.w = *(unsigned*)&d;
    }
    dst[(size_t)h * HW + p0]     = r0;
    dst[(size_t)h * HW + p0 + 1] = r1;
}

// ============================================================================
// Kernel 2: flash attention on HMMA, key-split 4 ways (occupancy: 1024 blocks,
// ~55 warps/SM). Block = 256 thr (8 warps), warp owns 16 queries; block covers
// 128 queries of one head over 1024 keys. grid = (32, 8, 4).
// Constant-bias softmax => partials across key slices add exactly.
// Denominator via extra mma against ones (exact row-sum of the same f16 P).
// ============================================================================
__global__ __launch_bounds__(256)
void attn_kernel(const float* __restrict__ temperature) {
    __shared__ unsigned sK[CHUNK * 4];      // 4 KB
    __shared__ unsigned sVT[8 * CPAD];      // 4.2 KB

    const int h    = blockIdx.y;
    const int s    = blockIdx.z;
    const int tid  = threadIdx.x;
    const int wid  = tid >> 5;
    const int lane = tid & 31;
    const int r = lane >> 2, m = lane & 3;
    const int q0 = blockIdx.x * 128 + wid * 16;

    const float bias = -fabsf(temperature[h]) * 1.4426950408889634f;
    const unsigned ONES = 0x3C003C00u;

    const unsigned* qU = (const unsigned*)g_qh + (size_t)h * HW * 4;
    const unsigned a0q = qU[(q0 + r) * 4 + m];
    const unsigned a1q = qU[(q0 + r + 8) * 4 + m];

    float o0 = 0.f, o1 = 0.f, o2 = 0.f, o3 = 0.f;
    float dd0 = 0.f, dd1 = 0.f, dd2 = 0.f, dd3 = 0.f;

    const uint4*    gK4 = (const uint4*)((const unsigned*)g_kh + (size_t)h * HW * 4);
    const unsigned* gV  = (const unsigned*)g_vt + (size_t)h * 8 * (HW / 2);

    const int vd = tid >> 5;
    const int vj = (tid & 31) * 4;
    const int ch0 = s * (HW / KS / CHUNK);          // 4 chunks per split

    for (int ch = ch0; ch < ch0 + HW / KS / CHUNK; ch++) {
        __syncthreads();
        ((uint4*)sK)[tid] = gK4[ch * CHUNK + tid];
        *(uint4*)(sVT + vd * CPAD + vj) =
            *(const uint4*)(gV + vd * (HW / 2) + ch * (CHUNK / 2) + vj);
        __syncthreads();

#pragma unroll 4
        for (int kb = 0; kb < CHUNK; kb += 16) {
            const unsigned kb0 = sK[(kb + r) * 4 + m];
            const unsigned kb1 = sK[(kb + 8 + r) * 4 + m];

            float s0, s1, s2, s3, t0, t1, t2, t3;
            mma_s(s0, s1, s2, s3, a0q, a1q, kb0, bias);
            mma_s(t0, t1, t2, t3, a0q, a1q, kb1, bias);

            const unsigned p0 = ex2h2(packh2(s0, s1));
            const unsigned p1 = ex2h2(packh2(s2, s3));
            const unsigned p2 = ex2h2(packh2(t0, t1));
            const unsigned p3 = ex2h2(packh2(t2, t3));

            const unsigned vb0 = sVT[r * CPAD + (kb >> 1) + m];
            const unsigned vb1 = sVT[r * CPAD + (kb >> 1) + m + 4];
            mma16(o0, o1, o2, o3, p0, p1, p2, p3, vb0, vb1);
            mma16(dd0, dd1, dd2, dd3, p0, p1, p2, p3, ONES, ONES);
        }
    }

    float* pa = g_pacc + ((size_t)s * 64 + h * 8) * HW;
    pa[(2 * m    ) * HW + q0 + r    ] = o0;
    pa[(2 * m + 1) * HW + q0 + r    ] = o1;
    pa[(2 * m    ) * HW + q0 + r + 8] = o2;
    pa[(2 * m + 1) * HW + q0 + r + 8] = o3;
    if (m == 0) {   // dd0/dd2 identical across the quad (B = ones)
        float* pd = g_pden + ((size_t)s * NH + h) * HW;
        pd[q0 + r    ] = dd0;
        pd[q0 + r + 8] = dd2;
    }
}

// ============================================================================
// Kernel 2b: reduce key-split partials + divide. Pure streaming, float4.
// grid = (8, 8), block = 128. Thread: one float4 pixel group of one head.
// ============================================================================
__global__ __launch_bounds__(128)
void reduce_kernel() {
    const int i4 = blockIdx.x * 128 + threadIdx.x;   // 0..1023
    const int h  = blockIdx.y;

    float4 acc[8];
#pragma unroll
    for (int d = 0; d < 8; d++) acc[d] = make_float4(0.f, 0.f, 0.f, 0.f);
    float4 den = make_float4(0.f, 0.f, 0.f, 0.f);

#pragma unroll
    for (int s = 0; s < KS; s++) {
        const float4 dn = ((const float4*)(g_pden + ((size_t)s * NH + h) * HW))[i4];
        den.x += dn.x; den.y += dn.y; den.z += dn.z; den.w += dn.w;
#pragma unroll
        for (int d = 0; d < 8; d++) {
            const float4 a = ((const float4*)(g_pacc + ((size_t)s * 64 + h * 8 + d) * HW))[i4];
            acc[d].x += a.x; acc[d].y += a.y; acc[d].z += a.z; acc[d].w += a.w;
        }
    }

    const float4 r = make_float4(1.f/den.x, 1.f/den.y, 1.f/den.z, 1.f/den.w);
#pragma unroll
    for (int d = 0; d < 8; d++) {
        float4 o = make_float4(acc[d].x*r.x, acc[d].y*r.y, acc[d].z*r.z, acc[d].w*r.w);
        ((float4*)(g_o + ((size_t)h * 8 + d) * HW))[i4] = o;
    }
}

// ============================================================================
// Kernel 3: output projection, two pixels per thread (float2).
// grid = (16, 8), block = 128.
// ============================================================================
__global__ __launch_bounds__(128)
void outproj_kernel(const float* __restrict__ wout, float* __restrict__ out) {
    __shared__ float sWT[64 * 8];
    const int tid = threadIdx.x;
    const int p0  = (blockIdx.x * 128 + tid) * 2;
    const int og  = blockIdx.y;

#pragma unroll
    for (int i = tid; i < 512; i += 128) {
        const int d = i >> 6, c = i & 63;
        sWT[c * 8 + d] = wout[(og * 8) * 64 + i];
    }
    __syncthreads();

    float accx[8], accy[8];
#pragma unroll
    for (int d = 0; d < 8; d++) { accx[d] = 0.f; accy[d] = 0.f; }

#pragma unroll
    for (int c = 0; c < 64; c++) {
        const float2 xv = *(const float2*)&g_o[c * HW + p0];
        const float4 w0 = *(const float4*)&sWT[c * 8];
        const float4 w1 = *(const float4*)&sWT[c * 8 + 4];
        accx[0] += w0.x * xv.x; accy[0] += w0.x * xv.y;
        accx[1] += w0.y * xv.x; accy[1] += w0.y * xv.y;
        accx[2] += w0.z * xv.x; accy[2] += w0.z * xv.y;
        accx[3] += w0.w * xv.x; accy[3] += w0.w * xv.y;
        accx[4] += w1.x * xv.x; accy[4] += w1.x * xv.y;
        accx[5] += w1.y * xv.x; accy[5] += w1.y * xv.y;
        accx[6] += w1.z * xv.x; accy[6] += w1.z * xv.y;
        accx[7] += w1.w * xv.x; accy[7] += w1.w * xv.y;
    }

#pragma unroll
    for (int d = 0; d < 8; d++)
        *(float2*)&out[(og * 8 + d) * HW + p0] = make_float2(accx[d], accy[d]);
}

// ============================================================================
extern "C" void kernel_launch(void* const* d_in, const int* in_sizes, int n_in,
                              void* d_out, int out_size) {
    const float* x    = (const float*)d_in[0];
    const float* y    = (const float*)d_in[1];
    const float* wq   = (const float*)d_in[2];
    const float* wkv  = (const float*)d_in[3];
    const float* wout = (const float*)d_in[4];
    const float* temp = (const float*)d_in[5];
    float* out = (float*)d_out;

    prep_kernel<<<dim3(16, 24), 128>>>(x, y, wq, wkv, temp);
    attn_kernel<<<dim3(32, 8, KS), 256>>>(temp);
    reduce_kernel<<<dim3(8, 8), 128>>>();
    outproj_kernel<<<dim3(16, 8), 128>>>(wout, out);
}

// round 13
// speedup vs baseline: 1.2573x; 1.0935x over previous
#include <cuda_runtime.h>
#include <cuda_fp16.h>

#define HW 4096          // tokens
#define NH 8             // heads
#define CHUNK 512        // keys per smem stage
#define CPAD 260         // padded uint stride for V^T rows (CHUNK/2 + 4)
#define KS 4             // key split for attention (partials add exactly)

// ---- scratch (device globals; no allocation allowed) ----
__device__ __align__(16) __half g_qh[NH * HW * 8];  // [h][n][8] f16, L2-norm * T*log2e
__device__ __align__(16) __half g_kh[NH * HW * 8];  // [h][m][8] f16, L2-norm
__device__ __align__(16) __half g_vt[NH * 8 * HW];  // [h][d][m] f16 (V transposed)
__device__ __align__(16) float g_pacc[KS * 64 * HW]; // partial numerators [s][h*8+d][p]
__device__ __align__(16) float g_pden[KS * NH * HW]; // partial denominators [s][h][p]
__device__ __align__(16) float g_o[64 * HW];         // reduced attention out [c][p]

// ---- async copy helpers ----
__device__ __forceinline__ void cp16(void* dst, const void* src) {
    unsigned daddr = (unsigned)__cvta_generic_to_shared(dst);
    asm volatile("cp.async.cg.shared.global [%0], [%1], 16;" :: "r"(daddr), "l"(src) : "memory");
}
#define CP_COMMIT() asm volatile("cp.async.commit_group;" ::: "memory")
#define CP_WAIT(n)  asm volatile("cp.async.wait_group %0;" :: "n"(n) : "memory")

// pack two f32 -> f16x2
__device__ __forceinline__ unsigned packh2(float lo, float hi) {
    unsigned r; asm("cvt.rn.f16x2.f32 %0,%1,%2;" : "=r"(r) : "f"(hi), "f"(lo)); return r;
}
// packed half2 exp2
__device__ __forceinline__ unsigned ex2h2(unsigned x) {
    unsigned r; asm("ex2.approx.f16x2 %0,%1;" : "=r"(r) : "r"(x)); return r;
}
// S-mma: m16n8k8 f16 inputs, f32 accumulate, scalar C broadcast (bias)
__device__ __forceinline__ void mma_s(float& d0, float& d1, float& d2, float& d3,
                                      unsigned a0, unsigned a1, unsigned b0,
                                      float c) {
    asm("mma.sync.aligned.m16n8k8.row.col.f32.f16.f16.f32 "
        "{%0,%1,%2,%3},{%4,%5},{%6},{%7,%7,%7,%7};"
        : "=f"(d0), "=f"(d1), "=f"(d2), "=f"(d3)
        : "r"(a0), "r"(a1), "r"(b0), "f"(c));
}
// m16n8k16 f16 mma, accumulates in place
__device__ __forceinline__ void mma16(float& d0, float& d1, float& d2, float& d3,
                                      unsigned a0, unsigned a1, unsigned a2, unsigned a3,
                                      unsigned b0, unsigned b1) {
    asm("mma.sync.aligned.m16n8k16.row.col.f32.f16.f16.f32 "
        "{%0,%1,%2,%3},{%4,%5,%6,%7},{%8,%9},{%0,%1,%2,%3};"
        : "+f"(d0), "+f"(d1), "+f"(d2), "+f"(d3)
        : "r"(a0), "r"(a1), "r"(a2), "r"(a3), "r"(b0), "r"(b1));
}

// ============================================================================
// Kernel 1: q/k/v projection + per-head L2 norm; emit f16.
// The 128-pixel x/y tile is STAGED IN SMEM via cp.async (one batched burst
// instead of 64 serial L2-latency loads per thread), then read via
// conflict-free LDS.32. grid = (32, 24), block = 128.
// ============================================================================
__global__ __launch_bounds__(128)
void prep_kernel(const float* __restrict__ x, const float* __restrict__ y,
                 const float* __restrict__ wq, const float* __restrict__ wkv,
                 const float* __restrict__ temperature) {
    __shared__ __align__(16) float sIn[64 * 128];   // [c][pix] 32 KB
    __shared__ float sWT[64 * 8];                   // [c][d]   2 KB
    const int tid   = threadIdx.x;
    const int pbase = blockIdx.x * 128;
    const int p     = pbase + tid;
    const int task  = blockIdx.y;
    const int typ   = task >> 3;      // 0=q, 1=k, 2=v
    const int h     = task & 7;

    const float* wrow;
    if (typ == 0)      wrow = wq  + (h * 8) * 64;
    else if (typ == 1) wrow = wkv + (h * 8) * 64;
    else               wrow = wkv + (64 + h * 8) * 64;
#pragma unroll
    for (int i = tid; i < 512; i += 128) {
        const int d = i >> 6, c = i & 63;
        sWT[c * 8 + d] = wrow[i];
    }

    const float* __restrict__ src = (typ == 0) ? x : y;
#pragma unroll
    for (int i = tid; i < 2048; i += 128) {          // 16 cp.async per thread
        const int c = i >> 5, j4 = i & 31;
        cp16(&((float4*)sIn)[i], (const float4*)(src + (size_t)c * HW + pbase) + j4);
    }
    CP_COMMIT(); CP_WAIT(0);
    __syncthreads();

    float acc[8];
#pragma unroll
    for (int d = 0; d < 8; d++) acc[d] = 0.f;

#pragma unroll
    for (int c = 0; c < 64; c++) {
        const float xv = sIn[c * 128 + tid];          // LDS.32, conflict-free
        const float4 w0 = *(const float4*)&sWT[c * 8];
        const float4 w1 = *(const float4*)&sWT[c * 8 + 4];
        acc[0] += w0.x * xv; acc[1] += w0.y * xv;
        acc[2] += w0.z * xv; acc[3] += w0.w * xv;
        acc[4] += w1.x * xv; acc[5] += w1.y * xv;
        acc[6] += w1.z * xv; acc[7] += w1.w * xv;
    }

    if (typ == 2) {
#pragma unroll
        for (int d = 0; d < 8; d++)
            g_vt[((size_t)h * 8 + d) * HW + p] = __float2half_rn(acc[d]);
        return;
    }

    float ss = 0.f;
#pragma unroll
    for (int d = 0; d < 8; d++) ss += acc[d] * acc[d];
    float scale = 1.f / fmaxf(sqrtf(ss), 1e-12f);
    if (typ == 0) scale *= temperature[h] * 1.4426950408889634f;

    __half2 h01 = __floats2half2_rn(acc[0] * scale, acc[1] * scale);
    __half2 h23 = __floats2half2_rn(acc[2] * scale, acc[3] * scale);
    __half2 h45 = __floats2half2_rn(acc[4] * scale, acc[5] * scale);
    __half2 h67 = __floats2half2_rn(acc[6] * scale, acc[7] * scale);
    uint4 row;
    row.x = *(unsigned*)&h01; row.y = *(unsigned*)&h23;
    row.z = *(unsigned*)&h45; row.w = *(unsigned*)&h67;
    uint4* dst = (typ == 0) ? (uint4*)g_qh : (uint4*)g_kh;
    dst[(size_t)h * HW + p] = row;
}

// ============================================================================
// Kernel 2: flash attention on HMMA, key-split 4 ways, cp.async double-buffer.
// Block = 256 thr (8 warps), warp owns 16 queries; block covers 128 queries of
// one head over 1024 keys (= exactly 2 chunks of 512, both staged up front).
// grid = (32, 8, 4) = 1024 blocks.
// Constant-bias softmax => partials across key slices add exactly.
// Denominator via extra mma against ones (exact row-sum of the same f16 P).
// ============================================================================
__global__ __launch_bounds__(256)
void attn_kernel(const float* __restrict__ temperature) {
    __shared__ __align__(16) unsigned sK[2][CHUNK * 4];   // 8 KB each
    __shared__ __align__(16) unsigned sVT[2][8 * CPAD];   // 8.3 KB each

    const int h    = blockIdx.y;
    const int s    = blockIdx.z;
    const int tid  = threadIdx.x;
    const int wid  = tid >> 5;
    const int lane = tid & 31;
    const int r = lane >> 2, m = lane & 3;
    const int q0 = blockIdx.x * 128 + wid * 16;

    const float bias = -fabsf(temperature[h]) * 1.4426950408889634f;
    const unsigned ONES = 0x3C003C00u;

    const unsigned* qU = (const unsigned*)g_qh + (size_t)h * HW * 4;
    const unsigned a0q = qU[(q0 + r) * 4 + m];
    const unsigned a1q = qU[(q0 + r + 8) * 4 + m];

    float o0 = 0.f, o1 = 0.f, o2 = 0.f, o3 = 0.f;
    float dd0 = 0.f, dd1 = 0.f, dd2 = 0.f, dd3 = 0.f;

    const uint4*    gK4 = (const uint4*)((const unsigned*)g_kh + (size_t)h * HW * 4);
    const unsigned* gV  = (const unsigned*)g_vt + (size_t)h * 8 * (HW / 2);

    const int ch0 = s * 2;     // 2 chunks of 512 per block

    // stage both chunks up front: chunk ch0 -> buf0 (group 1), ch0+1 -> buf1 (group 2)
#pragma unroll
    for (int b = 0; b < 2; b++) {
        const int ch = ch0 + b;
#pragma unroll
        for (int i = tid; i < CHUNK; i += 256)
            cp16(&((uint4*)sK[b])[i], &gK4[ch * CHUNK + i]);
#pragma unroll
        for (int i = tid; i < 512; i += 256) {
            const int row = i >> 6, c16 = i & 63;
            cp16((uint4*)(sVT[b] + row * CPAD + c16 * 4),
                 (const uint4*)(gV + row * (HW / 2) + ch * (CHUNK / 2) + c16 * 4));
        }
        CP_COMMIT();
    }

#pragma unroll
    for (int b = 0; b < 2; b++) {
        if (b == 0) { CP_WAIT(1); } else { CP_WAIT(0); }
        __syncthreads();

        const unsigned* bK = sK[b];
        const unsigned* bV = sVT[b];
#pragma unroll 4
        for (int kb = 0; kb < CHUNK; kb += 16) {
            const unsigned kb0 = bK[(kb + r) * 4 + m];
            const unsigned kb1 = bK[(kb + 8 + r) * 4 + m];

            float s0, s1, s2, s3, t0, t1, t2, t3;
            mma_s(s0, s1, s2, s3, a0q, a1q, kb0, bias);
            mma_s(t0, t1, t2, t3, a0q, a1q, kb1, bias);

            const unsigned p0 = ex2h2(packh2(s0, s1));
            const unsigned p1 = ex2h2(packh2(s2, s3));
            const unsigned p2 = ex2h2(packh2(t0, t1));
            const unsigned p3 = ex2h2(packh2(t2, t3));

            const unsigned vb0 = bV[r * CPAD + (kb >> 1) + m];
            const unsigned vb1 = bV[r * CPAD + (kb >> 1) + m + 4];
            mma16(o0, o1, o2, o3, p0, p1, p2, p3, vb0, vb1);
            mma16(dd0, dd1, dd2, dd3, p0, p1, p2, p3, ONES, ONES);
        }
    }

    float* pa = g_pacc + ((size_t)s * 64 + h * 8) * HW;
    pa[(2 * m    ) * HW + q0 + r    ] = o0;
    pa[(2 * m + 1) * HW + q0 + r    ] = o1;
    pa[(2 * m    ) * HW + q0 + r + 8] = o2;
    pa[(2 * m + 1) * HW + q0 + r + 8] = o3;
    if (m == 0) {   // dd0/dd2 identical across the quad (B = ones)
        float* pd = g_pden + ((size_t)s * NH + h) * HW;
        pd[q0 + r    ] = dd0;
        pd[q0 + r + 8] = dd2;
    }
}

// ============================================================================
// Kernel 2b: reduce key-split partials + divide. One thread per
// (channel, float4 pixel group) = 64K threads. grid = 512, block = 128.
// ============================================================================
__global__ __launch_bounds__(128)
void reduce_kernel() {
    const int gid = blockIdx.x * 128 + threadIdx.x;   // 0..65535
    const int i4  = gid & 1023;                       // float4 group in pixel dim
    const int c   = gid >> 10;                        // channel 0..63
    const int h   = c >> 3;

    float4 acc = make_float4(0.f, 0.f, 0.f, 0.f);
    float4 den = make_float4(0.f, 0.f, 0.f, 0.f);
#pragma unroll
    for (int s = 0; s < KS; s++) {
        const float4 a = ((const float4*)g_pacc)[((size_t)s * 64 + c) * 1024 + i4];
        acc.x += a.x; acc.y += a.y; acc.z += a.z; acc.w += a.w;
        const float4 d = ((const float4*)g_pden)[((size_t)s * NH + h) * 1024 + i4];
        den.x += d.x; den.y += d.y; den.z += d.z; den.w += d.w;
    }
    ((float4*)g_o)[(size_t)c * 1024 + i4] =
        make_float4(acc.x / den.x, acc.y / den.y, acc.z / den.z, acc.w / den.w);
}

// ============================================================================
// Kernel 3: output projection with smem-staged input tile (same pattern as
// prep). grid = (32, 8), block = 128.
// ============================================================================
__global__ __launch_bounds__(128)
void outproj_kernel(const float* __restrict__ wout, float* __restrict__ out) {
    __shared__ __align__(16) float sIn[64 * 128];   // 32 KB
    __shared__ float sWT[64 * 8];
    const int tid   = threadIdx.x;
    const int pbase = blockIdx.x * 128;
    const int p     = pbase + tid;
    const int og    = blockIdx.y;

#pragma unroll
    for (int i = tid; i < 512; i += 128) {
        const int d = i >> 6, c = i & 63;
        sWT[c * 8 + d] = wout[(og * 8) * 64 + i];
    }
#pragma unroll
    for (int i = tid; i < 2048; i += 128) {
        const int c = i >> 5, j4 = i & 31;
        cp16(&((float4*)sIn)[i], (const float4*)(g_o + (size_t)c * HW + pbase) + j4);
    }
    CP_COMMIT(); CP_WAIT(0);
    __syncthreads();

    float acc[8];
#pragma unroll
    for (int d = 0; d < 8; d++) acc[d] = 0.f;

#pragma unroll
    for (int c = 0; c < 64; c++) {
        const float xv = sIn[c * 128 + tid];
        const float4 w0 = *(const float4*)&sWT[c * 8];
        const float4 w1 = *(const float4*)&sWT[c * 8 + 4];
        acc[0] += w0.x * xv; acc[1] += w0.y * xv;
        acc[2] += w0.z * xv; acc[3] += w0.w * xv;
        acc[4] += w1.x * xv; acc[5] += w1.y * xv;
        acc[6] += w1.z * xv; acc[7] += w1.w * xv;
    }

#pragma unroll
    for (int d = 0; d < 8; d++)
        out[(og * 8 + d) * HW + p] = acc[d];
}

// ============================================================================
extern "C" void kernel_launch(void* const* d_in, const int* in_sizes, int n_in,
                              void* d_out, int out_size) {
    const float* x    = (const float*)d_in[0];
    const float* y    = (const float*)d_in[1];
    const float* wq   = (const float*)d_in[2];
    const float* wkv  = (const float*)d_in[3];
    const float* wout = (const float*)d_in[4];
    const float* temp = (const float*)d_in[5];
    float* out = (float*)d_out;

    prep_kernel<<<dim3(32, 24), 128>>>(x, y, wq, wkv, temp);
    attn_kernel<<<dim3(32, 8, KS), 256>>>(temp);
    reduce_kernel<<<512, 128>>>();
    outproj_kernel<<<dim3(32, 8), 128>>>(wout, out);
}

// round 14
// speedup vs baseline: 1.3348x; 1.0616x over previous
#include <cuda_runtime.h>
#include <cuda_fp16.h>

#define HW 4096          // tokens
#define NH 8             // heads
#define CHUNK 512        // keys per smem stage
#define CPAD 260         // padded uint stride for V^T rows (CHUNK/2 + 4)
#define KS 4             // key split for attention (partials add exactly)
#define FPIX 32          // pixels per finish block

// ---- scratch (device globals; no allocation allowed) ----
__device__ __align__(16) __half g_qh[NH * HW * 8];   // [h][n][8] f16, L2-norm * T*log2e
__device__ __align__(16) __half g_kh[NH * HW * 8];   // [h][m][8] f16, L2-norm
__device__ __align__(16) __half g_vt[NH * 8 * HW];   // [h][d][m] f16 (V transposed)
__device__ __align__(16) float g_pacct[KS * HW * 64]; // partial numerators [s][p][c]  (TRANSPOSED)
__device__ __align__(16) float g_pden[KS * NH * HW];  // partial denominators [s][h][p]

// ---- async copy helpers ----
__device__ __forceinline__ void cp16(void* dst, const void* src) {
    unsigned daddr = (unsigned)__cvta_generic_to_shared(dst);
    asm volatile("cp.async.cg.shared.global [%0], [%1], 16;" :: "r"(daddr), "l"(src) : "memory");
}
#define CP_COMMIT() asm volatile("cp.async.commit_group;" ::: "memory")
#define CP_WAIT(n)  asm volatile("cp.async.wait_group %0;" :: "n"(n) : "memory")

// pack two f32 -> f16x2
__device__ __forceinline__ unsigned packh2(float lo, float hi) {
    unsigned r; asm("cvt.rn.f16x2.f32 %0,%1,%2;" : "=r"(r) : "f"(hi), "f"(lo)); return r;
}
// packed half2 exp2
__device__ __forceinline__ unsigned ex2h2(unsigned x) {
    unsigned r; asm("ex2.approx.f16x2 %0,%1;" : "=r"(r) : "r"(x)); return r;
}
// S-mma: m16n8k8 f16 inputs, f32 accumulate, scalar C broadcast (bias)
__device__ __forceinline__ void mma_s(float& d0, float& d1, float& d2, float& d3,
                                      unsigned a0, unsigned a1, unsigned b0,
                                      float c) {
    asm("mma.sync.aligned.m16n8k8.row.col.f32.f16.f16.f32 "
        "{%0,%1,%2,%3},{%4,%5},{%6},{%7,%7,%7,%7};"
        : "=f"(d0), "=f"(d1), "=f"(d2), "=f"(d3)
        : "r"(a0), "r"(a1), "r"(b0), "f"(c));
}
// m16n8k16 f16 mma, accumulates in place
__device__ __forceinline__ void mma16(float& d0, float& d1, float& d2, float& d3,
                                      unsigned a0, unsigned a1, unsigned a2, unsigned a3,
                                      unsigned b0, unsigned b1) {
    asm("mma.sync.aligned.m16n8k16.row.col.f32.f16.f16.f32 "
        "{%0,%1,%2,%3},{%4,%5,%6,%7},{%8,%9},{%0,%1,%2,%3};"
        : "+f"(d0), "+f"(d1), "+f"(d2), "+f"(d3)
        : "r"(a0), "r"(a1), "r"(a2), "r"(a3), "r"(b0), "r"(b1));
}

// ============================================================================
// Kernel 1: q/k/v projection + per-head L2 norm; emit f16.
// 128-pixel tile staged in smem via cp.async; conflict-free LDS.
// grid = (32, 24), block = 128.
// ============================================================================
__global__ __launch_bounds__(128)
void prep_kernel(const float* __restrict__ x, const float* __restrict__ y,
                 const float* __restrict__ wq, const float* __restrict__ wkv,
                 const float* __restrict__ temperature) {
    __shared__ __align__(16) float sIn[64 * 128];   // 32 KB
    __shared__ float sWT[64 * 8];                   // 2 KB
    const int tid   = threadIdx.x;
    const int pbase = blockIdx.x * 128;
    const int p     = pbase + tid;
    const int task  = blockIdx.y;
    const int typ   = task >> 3;      // 0=q, 1=k, 2=v
    const int h     = task & 7;

    const float* wrow;
    if (typ == 0)      wrow = wq  + (h * 8) * 64;
    else if (typ == 1) wrow = wkv + (h * 8) * 64;
    else               wrow = wkv + (64 + h * 8) * 64;
#pragma unroll
    for (int i = tid; i < 512; i += 128) {
        const int d = i >> 6, c = i & 63;
        sWT[c * 8 + d] = wrow[i];
    }

    const float* __restrict__ src = (typ == 0) ? x : y;
#pragma unroll
    for (int i = tid; i < 2048; i += 128) {
        const int c = i >> 5, j4 = i & 31;
        cp16(&((float4*)sIn)[i], (const float4*)(src + (size_t)c * HW + pbase) + j4);
    }
    CP_COMMIT(); CP_WAIT(0);
    __syncthreads();

    float acc[8];
#pragma unroll
    for (int d = 0; d < 8; d++) acc[d] = 0.f;

#pragma unroll
    for (int c = 0; c < 64; c++) {
        const float xv = sIn[c * 128 + tid];
        const float4 w0 = *(const float4*)&sWT[c * 8];
        const float4 w1 = *(const float4*)&sWT[c * 8 + 4];
        acc[0] += w0.x * xv; acc[1] += w0.y * xv;
        acc[2] += w0.z * xv; acc[3] += w0.w * xv;
        acc[4] += w1.x * xv; acc[5] += w1.y * xv;
        acc[6] += w1.z * xv; acc[7] += w1.w * xv;
    }

    if (typ == 2) {
#pragma unroll
        for (int d = 0; d < 8; d++)
            g_vt[((size_t)h * 8 + d) * HW + p] = __float2half_rn(acc[d]);
        return;
    }

    float ss = 0.f;
#pragma unroll
    for (int d = 0; d < 8; d++) ss += acc[d] * acc[d];
    float scale = 1.f / fmaxf(sqrtf(ss), 1e-12f);
    if (typ == 0) scale *= temperature[h] * 1.4426950408889634f;

    __half2 h01 = __floats2half2_rn(acc[0] * scale, acc[1] * scale);
    __half2 h23 = __floats2half2_rn(acc[2] * scale, acc[3] * scale);
    __half2 h45 = __floats2half2_rn(acc[4] * scale, acc[5] * scale);
    __half2 h67 = __floats2half2_rn(acc[6] * scale, acc[7] * scale);
    uint4 row;
    row.x = *(unsigned*)&h01; row.y = *(unsigned*)&h23;
    row.z = *(unsigned*)&h45; row.w = *(unsigned*)&h67;
    uint4* dst = (typ == 0) ? (uint4*)g_qh : (uint4*)g_kh;
    dst[(size_t)h * HW + p] = row;
}

// ============================================================================
// Kernel 2: flash attention on HMMA, key-split 4 ways, cp.async double-buffer.
// Block = 256 thr (8 warps); 128 queries of one head over 1024 keys.
// grid = (32, 8, 4). Constant-bias softmax => partials add exactly.
// Epilogue writes TRANSPOSED partials g_pacct[s][p][c] (float2, coalesced
// 32B segments) for the HMMA finish kernel.
// ============================================================================
__global__ __launch_bounds__(256)
void attn_kernel(const float* __restrict__ temperature) {
    __shared__ __align__(16) unsigned sK[2][CHUNK * 4];   // 8 KB each
    __shared__ __align__(16) unsigned sVT[2][8 * CPAD];   // 8.3 KB each

    const int h    = blockIdx.y;
    const int s    = blockIdx.z;
    const int tid  = threadIdx.x;
    const int wid  = tid >> 5;
    const int lane = tid & 31;
    const int r = lane >> 2, m = lane & 3;
    const int q0 = blockIdx.x * 128 + wid * 16;

    const float bias = -fabsf(temperature[h]) * 1.4426950408889634f;
    const unsigned ONES = 0x3C003C00u;

    const unsigned* qU = (const unsigned*)g_qh + (size_t)h * HW * 4;
    const unsigned a0q = qU[(q0 + r) * 4 + m];
    const unsigned a1q = qU[(q0 + r + 8) * 4 + m];

    float o0 = 0.f, o1 = 0.f, o2 = 0.f, o3 = 0.f;
    float dd0 = 0.f, dd1 = 0.f, dd2 = 0.f, dd3 = 0.f;

    const uint4*    gK4 = (const uint4*)((const unsigned*)g_kh + (size_t)h * HW * 4);
    const unsigned* gV  = (const unsigned*)g_vt + (size_t)h * 8 * (HW / 2);

    const int ch0 = s * 2;     // 2 chunks of 512 per block

#pragma unroll
    for (int b = 0; b < 2; b++) {
        const int ch = ch0 + b;
#pragma unroll
        for (int i = tid; i < CHUNK; i += 256)
            cp16(&((uint4*)sK[b])[i], &gK4[ch * CHUNK + i]);
#pragma unroll
        for (int i = tid; i < 512; i += 256) {
            const int row = i >> 6, c16 = i & 63;
            cp16((uint4*)(sVT[b] + row * CPAD + c16 * 4),
                 (const uint4*)(gV + row * (HW / 2) + ch * (CHUNK / 2) + c16 * 4));
        }
        CP_COMMIT();
    }

#pragma unroll
    for (int b = 0; b < 2; b++) {
        if (b == 0) { CP_WAIT(1); } else { CP_WAIT(0); }
        __syncthreads();

        const unsigned* bK = sK[b];
        const unsigned* bV = sVT[b];
#pragma unroll 4
        for (int kb = 0; kb < CHUNK; kb += 16) {
            const unsigned kb0 = bK[(kb + r) * 4 + m];
            const unsigned kb1 = bK[(kb + 8 + r) * 4 + m];

            float s0, s1, s2, s3, t0, t1, t2, t3;
            mma_s(s0, s1, s2, s3, a0q, a1q, kb0, bias);
            mma_s(t0, t1, t2, t3, a0q, a1q, kb1, bias);

            const unsigned p0 = ex2h2(packh2(s0, s1));
            const unsigned p1 = ex2h2(packh2(s2, s3));
            const unsigned p2 = ex2h2(packh2(t0, t1));
            const unsigned p3 = ex2h2(packh2(t2, t3));

            const unsigned vb0 = bV[r * CPAD + (kb >> 1) + m];
            const unsigned vb1 = bV[r * CPAD + (kb >> 1) + m + 4];
            mma16(o0, o1, o2, o3, p0, p1, p2, p3, vb0, vb1);
            mma16(dd0, dd1, dd2, dd3, p0, p1, p2, p3, ONES, ONES);
        }
    }

    // transposed partial writes: [s][p][c], dims pairs contiguous -> STG.64
    float* pa = g_pacct + (size_t)s * (HW * 64);
    *(float2*)&pa[(size_t)(q0 + r    ) * 64 + h * 8 + 2 * m] = make_float2(o0, o1);
    *(float2*)&pa[(size_t)(q0 + r + 8) * 64 + h * 8 + 2 * m] = make_float2(o2, o3);
    if (m == 0) {   // dd0/dd2 identical across the quad (B = ones)
        float* pd = g_pden + ((size_t)s * NH + h) * HW;
        pd[q0 + r    ] = dd0;
        pd[q0 + r + 8] = dd2;
    }
}

// ============================================================================
// Kernel 3: fused reduce + output projection on HMMA.
// Block = 256 thr (8 warps), FPIX=32 pixels; grid = 128.
// Staging: sum KS split-partials, multiply by 1/den, cvt f16 -> sB[p][c].
// W -> f16 smem. Then out[64 x 32] = W(m=64,k=64) @ B(k=64,n=32) via
// m16n8k16 mmas, f32 accumulate, STG.64 epilogue.
// ============================================================================
__global__ __launch_bounds__(256)
void finish_kernel(const float* __restrict__ wout, float* __restrict__ out) {
    __shared__ unsigned sW[64 * 36];     // f16 pairs [o][36 u32-pairs], 9 KB
    __shared__ unsigned sB[FPIX * 36];   // f16 pairs [p][36], 4.5 KB
    __shared__ float sRden[NH * FPIX];   // 1 KB
    const int tid   = threadIdx.x;
    const int pbase = blockIdx.x * FPIX;

    // W -> f16 smem (pairs along c). Coalesced LDG.64, conflict-free STS.
#pragma unroll
    for (int i = tid; i < 64 * 32; i += 256) {
        const int o = i >> 5, cp = i & 31;
        const float2 w = *(const float2*)&wout[o * 64 + cp * 2];
        sW[o * 36 + cp] = packh2(w.x, w.y);
    }

    // reciprocal denominators: 64 threads, one (head, float4-group) each
    if (tid < NH * (FPIX / 4)) {
        const int h = tid >> 3, g = tid & 7;
        float4 d = make_float4(0.f, 0.f, 0.f, 0.f);
#pragma unroll
        for (int s = 0; s < KS; s++) {
            const float4 v = *(const float4*)&g_pden[((size_t)s * NH + h) * HW + pbase + g * 4];
            d.x += v.x; d.y += v.y; d.z += v.z; d.w += v.w;
        }
        *(float4*)&sRden[h * FPIX + g * 4] =
            make_float4(1.f / d.x, 1.f / d.y, 1.f / d.z, 1.f / d.w);
    }
    __syncthreads();

    // sum partials, divide, convert -> sB[p][c] f16
#pragma unroll
    for (int i = tid; i < FPIX * 16; i += 256) {
        const int p = i >> 4, cg = i & 15;    // float4 channel group
        float4 a = make_float4(0.f, 0.f, 0.f, 0.f);
#pragma unroll
        for (int s = 0; s < KS; s++) {
            const float4 v = *(const float4*)
                &g_pacct[(size_t)s * (HW * 64) + (size_t)(pbase + p) * 64 + cg * 4];
            a.x += v.x; a.y += v.y; a.z += v.z; a.w += v.w;
        }
        const float rd = sRden[(cg >> 1) * FPIX + p];   // head = (4*cg)/8 = cg>>1
        sB[p * 36 + cg * 2]     = packh2(a.x * rd, a.y * rd);
        sB[p * 36 + cg * 2 + 1] = packh2(a.z * rd, a.w * rd);
    }
    __syncthreads();

    // mma phase: warp w -> m-tile (w&3), n-tiles {2*(w>>2), 2*(w>>2)+1}
    const int w    = tid >> 5;
    const int lane = tid & 31;
    const int r = lane >> 2, m4 = lane & 3;
    const int mrow = (w & 3) * 16;
    const int nt0  = (w >> 2) * 2;

    unsigned A[4][4];
#pragma unroll
    for (int k = 0; k < 4; k++) {
        A[k][0] = sW[(mrow + r    ) * 36 + 8 * k + m4];
        A[k][1] = sW[(mrow + r + 8) * 36 + 8 * k + m4];
        A[k][2] = sW[(mrow + r    ) * 36 + 8 * k + m4 + 4];
        A[k][3] = sW[(mrow + r + 8) * 36 + 8 * k + m4 + 4];
    }

#pragma unroll
    for (int nt = nt0; nt < nt0 + 2; nt++) {
        float d0 = 0.f, d1 = 0.f, d2 = 0.f, d3 = 0.f;
#pragma unroll
        for (int k = 0; k < 4; k++) {
            const unsigned b0 = sB[(nt * 8 + r) * 36 + 8 * k + m4];
            const unsigned b1 = sB[(nt * 8 + r) * 36 + 8 * k + m4 + 4];
            mma16(d0, d1, d2, d3, A[k][0], A[k][1], A[k][2], A[k][3], b0, b1);
        }
        const int pcol = pbase + nt * 8 + 2 * m4;
        *(float2*)&out[(size_t)(mrow + r    ) * HW + pcol] = make_float2(d0, d1);
        *(float2*)&out[(size_t)(mrow + r + 8) * HW + pcol] = make_float2(d2, d3);
    }
}

// ============================================================================
extern "C" void kernel_launch(void* const* d_in, const int* in_sizes, int n_in,
                              void* d_out, int out_size) {
    const float* x    = (const float*)d_in[0];
    const float* y    = (const float*)d_in[1];
    const float* wq   = (const float*)d_in[2];
    const float* wkv  = (const float*)d_in[3];
    const float* wout = (const float*)d_in[4];
    const float* temp = (const float*)d_in[5];
    float* out = (float*)d_out;

    prep_kernel<<<dim3(32, 24), 128>>>(x, y, wq, wkv, temp);
    attn_kernel<<<dim3(32, 8, KS), 256>>>(temp);
    finish_kernel<<<128, 256>>>(wout, out);
}